// round 6
// baseline (speedup 1.0000x reference)
#include <cuda_runtime.h>
#include <math.h>

#define D_DIM   512
#define N_WAY   64
#define NTHR    256
#define TM      4           // rows per thread (strided by 64)
#define TN      16          // cols per thread
#define ROWS_PER_TILE 256   // (NTHR/4) row-groups * TM
#define K_TILE  64
#define NK_TILES (D_DIM / K_TILE)        // 8
#define K4_PER_TILE (K_TILE / 4)         // 16
#define SX_STRIDE4 257                   // float4 stride between k4-rows (odd -> STS spread)
#define SP_FLOATS (D_DIM * N_WAY)        // 32768 floats = 128 KB (protos, k-major)
#define SX_FLOAT4 (K4_PER_TILE * SX_STRIDE4)  // 4112 float4 = 65792 B
#define SMEM_BYTES (SP_FLOATS * 4 + SX_FLOAT4 * 16 + N_WAY * 4)

__device__ float g_pn[N_WAY];

// ---------------------------------------------------------------------------
// Prep: per-prototype L2 norms (trivial).
// ---------------------------------------------------------------------------
__global__ void proto_norm_kernel(const float* __restrict__ protos) {
    __shared__ float red[128];
    int c = blockIdx.x, t = threadIdx.x;
    const float* p = protos + c * D_DIM;
    float s = 0.f;
    for (int k = t; k < D_DIM; k += 128) { float v = p[k]; s = fmaf(v, v, s); }
    red[t] = s;
    __syncthreads();
    for (int off = 64; off > 0; off >>= 1) {
        if (t < off) red[t] += red[t + off];
        __syncthreads();
    }
    if (t == 0) g_pn[c] = sqrtf(red[0]);
}

__device__ __forceinline__ unsigned long long pack_dup(float v) {
    unsigned long long r;
    asm("mov.b64 %0, {%1, %1};" : "=l"(r) : "f"(v));
    return r;
}
__device__ __forceinline__ unsigned long long pack2(float a, float b) {
    unsigned long long r;
    asm("mov.b64 %0, {%1, %2};" : "=l"(r) : "f"(a), "f"(b));
    return r;
}
#define FMA2(acc, a, b) asm("fma.rn.f32x2 %0, %1, %2, %0;" : "+l"(acc) : "l"(a), "l"(b))

// ---------------------------------------------------------------------------
// Main GEMM-style kernel. Persistent CTAs, TM=4 x TN=16 register tile,
// packed f32x2 FMA, x staged through smem with register prefetch.
// ---------------------------------------------------------------------------
__global__ __launch_bounds__(NTHR, 1)
void cosine_kernel(const float* __restrict__ x,
                   const float* __restrict__ protos,
                   float* __restrict__ out,
                   int nTiles) {
    extern __shared__ float smem[];
    float*  sp  = smem;                                   // [512][64] protos k-major
    float4* sx4 = reinterpret_cast<float4*>(smem + SP_FLOATS); // [16 k4][257] x tile
    float*  spn = smem + SP_FLOATS + SX_FLOAT4 * 4;       // [64]

    const int tid = threadIdx.x;
    const int cg  = tid & 3;    // col group: cols cg*16 .. cg*16+15
    const int rg  = tid >> 2;   // row group: rows rg, rg+64, rg+128, rg+192

    // One-time: protos transposed into smem (conflict-free STS).
    for (int i = tid; i < SP_FLOATS; i += NTHR) {
        int c = i & (N_WAY - 1);
        int k = i >> 6;
        sp[k * N_WAY + c] = protos[c * D_DIM + k];
    }
    if (tid < N_WAY) spn[tid] = g_pn[tid];

    const float4* xg = reinterpret_cast<const float4*>(x);  // row stride = 128 float4

    for (int tile = blockIdx.x; tile < nTiles; tile += gridDim.x) {
        const int rowbase = tile * ROWS_PER_TILE;

        unsigned long long acc[TM][TN / 2];
        #pragma unroll
        for (int j = 0; j < TM; ++j)
            #pragma unroll
            for (int q = 0; q < TN / 2; ++q) acc[j][q] = 0ull;
        unsigned long long xsq01 = 0ull, xsq23 = 0ull;

        // Prefetch k-tile 0 into registers (coalesced).
        float4 pf[16];
        #pragma unroll
        for (int i = 0; i < 16; ++i) {
            int f = tid + NTHR * i;
            int r = f >> 4, k4 = f & 15;
            pf[i] = xg[(size_t)(rowbase + r) * (D_DIM / 4) + k4];
        }

        for (int kt = 0; kt < NK_TILES; ++kt) {
            __syncthreads();  // previous compute done reading sx (and sp fill on first pass)
            #pragma unroll
            for (int i = 0; i < 16; ++i) {
                int f = tid + NTHR * i;
                int r = f >> 4, k4 = f & 15;
                sx4[k4 * SX_STRIDE4 + r] = pf[i];   // STS.128
            }
            __syncthreads();

            if (kt + 1 < NK_TILES) {   // prefetch next tile; latency hides under compute
                #pragma unroll
                for (int i = 0; i < 16; ++i) {
                    int f = tid + NTHR * i;
                    int r = f >> 4, k4 = f & 15;
                    pf[i] = xg[(size_t)(rowbase + r) * (D_DIM / 4) + (kt + 1) * 16 + k4];
                }
            }

            const float* prow_base = sp + (kt * K_TILE) * N_WAY + cg * TN;

            #pragma unroll 1
            for (int kq = 0; kq < K4_PER_TILE; ++kq) {
                // 4 rows' float4 (4 k's each); strided rows -> conflict-free LDS.128
                float4 xr[TM];
                #pragma unroll
                for (int j = 0; j < TM; ++j)
                    xr[j] = sx4[kq * SX_STRIDE4 + rg + 64 * j];

                const float* prow = prow_base + kq * 4 * N_WAY;
                #pragma unroll
                for (int kk = 0; kk < 4; ++kk) {
                    float xs[TM];
                    xs[0] = (kk == 0) ? xr[0].x : (kk == 1) ? xr[0].y : (kk == 2) ? xr[0].z : xr[0].w;
                    xs[1] = (kk == 0) ? xr[1].x : (kk == 1) ? xr[1].y : (kk == 2) ? xr[1].z : xr[1].w;
                    xs[2] = (kk == 0) ? xr[2].x : (kk == 1) ? xr[2].y : (kk == 2) ? xr[2].z : xr[2].w;
                    xs[3] = (kk == 0) ? xr[3].x : (kk == 1) ? xr[3].y : (kk == 2) ? xr[3].z : xr[3].w;

                    unsigned long long p01 = pack2(xs[0], xs[1]);
                    unsigned long long p23 = pack2(xs[2], xs[3]);
                    FMA2(xsq01, p01, p01);
                    FMA2(xsq23, p23, p23);

                    unsigned long long xp[TM];
                    #pragma unroll
                    for (int j = 0; j < TM; ++j) xp[j] = pack_dup(xs[j]);

                    const float* pk = prow + kk * N_WAY;
                    #pragma unroll
                    for (int qi = 0; qi < 4; ++qi) {
                        int q = (qi + cg) & 3;  // cg-rotated order -> conflict-free LDS
                        ulonglong2 pp = *reinterpret_cast<const ulonglong2*>(pk + 4 * q);
                        #pragma unroll
                        for (int j = 0; j < TM; ++j) {
                            FMA2(acc[j][2 * q],     xp[j], pp.x);
                            FMA2(acc[j][2 * q + 1], xp[j], pp.y);
                        }
                    }
                }
            }
        }

        // Epilogue: norms + normalize + store.
        float nx[TM];
        {
            float a, b, c, d;
            asm("mov.b64 {%0, %1}, %2;" : "=f"(a), "=f"(b) : "l"(xsq01));
            asm("mov.b64 {%0, %1}, %2;" : "=f"(c), "=f"(d) : "l"(xsq23));
            nx[0] = sqrtf(a); nx[1] = sqrtf(b); nx[2] = sqrtf(c); nx[3] = sqrtf(d);
        }
        #pragma unroll
        for (int j = 0; j < TM; ++j) {
            const int row = rowbase + rg + 64 * j;
            float* orow = out + (size_t)row * N_WAY + cg * TN;
            #pragma unroll
            for (int q = 0; q < 4; ++q) {
                float a0, a1, a2, a3;
                asm("mov.b64 {%0, %1}, %2;" : "=f"(a0), "=f"(a1) : "l"(acc[j][2 * q]));
                asm("mov.b64 {%0, %1}, %2;" : "=f"(a2), "=f"(a3) : "l"(acc[j][2 * q + 1]));
                const float* pn = spn + cg * TN + 4 * q;
                float4 r;
                r.x = -a0 / fmaxf(nx[j] * pn[0], 1e-8f);
                r.y = -a1 / fmaxf(nx[j] * pn[1], 1e-8f);
                r.z = -a2 / fmaxf(nx[j] * pn[2], 1e-8f);
                r.w = -a3 / fmaxf(nx[j] * pn[3], 1e-8f);
                reinterpret_cast<float4*>(orow)[q] = r;
            }
        }
    }
}

// ---------------------------------------------------------------------------
extern "C" void kernel_launch(void* const* d_in, const int* in_sizes, int n_in,
                              void* d_out, int out_size) {
    const float* x      = (const float*)d_in[0];
    const float* protos = (const float*)d_in[1];
    float* out          = (float*)d_out;
    const int Brows = in_sizes[0] / D_DIM;
    const int nTiles = (Brows + ROWS_PER_TILE - 1) / ROWS_PER_TILE;

    int nsm = 148;
    cudaDeviceGetAttribute(&nsm, cudaDevAttrMultiProcessorCount, 0);
    int grid = nTiles < nsm ? nTiles : nsm;

    cudaFuncSetAttribute(cosine_kernel,
                         cudaFuncAttributeMaxDynamicSharedMemorySize,
                         (int)SMEM_BYTES);

    proto_norm_kernel<<<N_WAY, 128>>>(protos);
    cosine_kernel<<<grid, NTHR, SMEM_BYTES>>>(x, protos, out, nTiles);
}